// round 6
// baseline (speedup 1.0000x reference)
#include <cuda_runtime.h>
#include <cstdint>

// ---------------------------------------------------------------------------
// Problem constants
// ---------------------------------------------------------------------------
namespace {
constexpr int kHeads = 12;
constexpr int kTok   = 197;               // N_PATCH + 1
constexpr int kDim   = 768;
constexpr int kBatch = 64;
constexpr int kM     = kBatch * kTok;     // 12608
constexpr int kQkvN  = 3 * kDim;          // 2304
constexpr float kScale = 0.125f;          // hd^-0.5
}  // namespace

// Scratch (static device globals; no runtime allocation allowed)
__device__ float g_qkv[(size_t)kM * kQkvN];             // (B, N, 3C), tf32-rounded
__device__ float g_attn[(size_t)kM * kDim];             // (B, N, C), tf32-rounded
__device__ float g_rpb[(size_t)kHeads * kTok * kTok];   // (H, N, N)
__device__ float g_x[(size_t)kM * kDim];                // tf32-rounded x
__device__ float g_wqkv[(size_t)kQkvN * kDim];          // tf32-rounded qkv_w
__device__ float g_wproj[(size_t)kDim * kDim];          // tf32-rounded proj_w

__device__ __forceinline__ float tf32_rna(float x) {
  uint32_t r;
  asm("cvt.rna.tf32.f32 %0, %1;" : "=r"(r) : "f"(x));
  return __uint_as_float(r);
}

// ---------------------------------------------------------------------------
// Elementwise tf32 rounding (n divisible by 4)
// ---------------------------------------------------------------------------
__global__ void tf32_round_kernel(const float* __restrict__ in, float* __restrict__ out,
                                  int n4) {
  int i = blockIdx.x * blockDim.x + threadIdx.x;
  if (i >= n4) return;
  float4 v = ((const float4*)in)[i];
  v.x = tf32_rna(v.x); v.y = tf32_rna(v.y);
  v.z = tf32_rna(v.z); v.w = tf32_rna(v.w);
  ((float4*)out)[i] = v;
}

// ---------------------------------------------------------------------------
// Relative position bias expansion: g_rpb[h][i][j] = table[idx[i][j]][h]
// ---------------------------------------------------------------------------
__global__ void rpb_expand(const int* __restrict__ idx, const float* __restrict__ tbl) {
  int t = blockIdx.x * blockDim.x + threadIdx.x;
  if (t >= kTok * kTok) return;
  int id = idx[t];
#pragma unroll
  for (int h = 0; h < kHeads; h++)
    g_rpb[(size_t)h * kTok * kTok + t] = tbl[id * kHeads + h];
}

// ---------------------------------------------------------------------------
// mma.sync m16n8k8 tf32 helper (fragment conventions per PTX ISA)
// ---------------------------------------------------------------------------
__device__ __forceinline__ void mma_tf32(float (&d)[4], const float* a, const float* b) {
  uint32_t a0 = __float_as_uint(a[0]), a1 = __float_as_uint(a[1]);
  uint32_t a2 = __float_as_uint(a[2]), a3 = __float_as_uint(a[3]);
  uint32_t b0 = __float_as_uint(b[0]), b1 = __float_as_uint(b[1]);
  asm volatile(
      "mma.sync.aligned.m16n8k8.row.col.f32.tf32.tf32.f32 "
      "{%0,%1,%2,%3}, {%4,%5,%6,%7}, {%8,%9}, {%0,%1,%2,%3};"
      : "+f"(d[0]), "+f"(d[1]), "+f"(d[2]), "+f"(d[3])
      : "r"(a0), "r"(a1), "r"(a2), "r"(a3), "r"(b0), "r"(b1));
}

// ---------------------------------------------------------------------------
// TF32 tensor-core GEMM, cp.async 4-stage pipeline.
// __launch_bounds__(256, 2): cap regs at 128 so 2 CTAs co-reside per SM
// (smem 80KB x 2 = 160KB <= 228KB) -> 4 warps per scheduler for latency hiding.
// MODE 0 epilogue additionally rounds outputs to tf32 (consumed by attn mma).
// ---------------------------------------------------------------------------
namespace {
constexpr int kStages      = 4;
constexpr int kSmStride    = 20;
constexpr int kStageFloats = 2 * 128 * kSmStride;
constexpr int kGemmSmemBytes = kStages * kStageFloats * 4;  // 81920
}  // namespace

__device__ __forceinline__ void cp_async16(uint32_t dst, const void* src, bool pred) {
  int sz = pred ? 16 : 0;
  asm volatile("cp.async.ca.shared.global [%0], [%1], 16, %2;"
               :: "r"(dst), "l"(src), "r"(sz));
}
__device__ __forceinline__ void cp_commit() { asm volatile("cp.async.commit_group;"); }
__device__ __forceinline__ void cp_wait2()  { asm volatile("cp.async.wait_group 2;"); }

template <int MODE>
__global__ __launch_bounds__(256, 2)
void gemm_tf32_pipe(const float* __restrict__ A, const float* __restrict__ W,
                    float* __restrict__ C, int M, int K, int N,
                    const float* __restrict__ b0, const float* __restrict__ b1) {
  extern __shared__ float sm[];

  const int t    = threadIdx.x;
  const int lane = t & 31;
  const int wid  = t >> 5;
  const int wm   = (wid >> 2) * 64;
  const int wn   = (wid & 3) * 32;
  const int m0   = blockIdx.y * 128;
  const int n0   = blockIdx.x * 128;

  const uint32_t smem_base = (uint32_t)__cvta_generic_to_shared(sm);

  auto issue_stage = [&](int kb_idx) {
    int kb = kb_idx * 16;
    uint32_t uA = smem_base + (uint32_t)((kb_idx & 3) * kStageFloats) * 4;
    uint32_t uB = uA + 128 * kSmStride * 4;
#pragma unroll
    for (int i = 0; i < 2; i++) {
      int idx = t + i * 256;
      int row = idx >> 2;
      int c4  = (idx & 3) * 4;
      uint32_t soff = (uint32_t)(row * kSmStride + c4) * 4;
      int mg = m0 + row;
      cp_async16(uA + soff, A + (size_t)mg * K + kb + c4, mg < M);
      int ng = n0 + row;
      cp_async16(uB + soff, W + (size_t)ng * K + kb + c4, true);
    }
  };

  const int nkb = K / 16;
#pragma unroll
  for (int s = 0; s < kStages - 1; s++) {
    issue_stage(s);
    cp_commit();
  }

  float acc[4][4][4] = {};
  const int lm = lane >> 2;
  const int lk = lane & 3;

  for (int kb = 0; kb < nkb; kb++) {
    cp_wait2();
    __syncthreads();

    if (kb + kStages - 1 < nkb) issue_stage(kb + kStages - 1);
    cp_commit();

    const float* As = sm + (kb & 3) * kStageFloats;
    const float* Bs = As + 128 * kSmStride;

#pragma unroll
    for (int ks = 0; ks < 2; ks++) {
      float af[4][4];
      float bf[4][2];
#pragma unroll
      for (int mt = 0; mt < 4; mt++) {
        int r = wm + mt * 16 + lm;
        int c = ks * 8 + lk;
        af[mt][0] = As[r * kSmStride + c];
        af[mt][1] = As[(r + 8) * kSmStride + c];
        af[mt][2] = As[r * kSmStride + c + 4];
        af[mt][3] = As[(r + 8) * kSmStride + c + 4];
      }
#pragma unroll
      for (int nt = 0; nt < 4; nt++) {
        int r = wn + nt * 8 + lm;
        int c = ks * 8 + lk;
        bf[nt][0] = Bs[r * kSmStride + c];
        bf[nt][1] = Bs[r * kSmStride + c + 4];
      }
#pragma unroll
      for (int mt = 0; mt < 4; mt++)
#pragma unroll
        for (int nt = 0; nt < 4; nt++)
          mma_tf32(acc[mt][nt], af[mt], bf[nt]);
    }
  }

  const int mrow = lane >> 2;
  const int ncol = (lane & 3) * 2;
#pragma unroll
  for (int mt = 0; mt < 4; mt++) {
#pragma unroll
    for (int half = 0; half < 2; half++) {
      int m = m0 + wm + mt * 16 + mrow + half * 8;
      if (m >= M) continue;
#pragma unroll
      for (int nt = 0; nt < 4; nt++) {
        int n = n0 + wn + nt * 8 + ncol;
        float v0 = acc[mt][nt][half * 2 + 0];
        float v1 = acc[mt][nt][half * 2 + 1];
        if (MODE == 0) {
          float bias0 = (n < kDim) ? b0[n] : ((n < 2 * kDim) ? 0.f : b1[n - 2 * kDim]);
          float bias1 = (n + 1 < kDim) ? b0[n + 1]
                        : ((n + 1 < 2 * kDim) ? 0.f : b1[n + 1 - 2 * kDim]);
          v0 += bias0;
          v1 += bias1;
          if (n < kDim) { v0 *= kScale; v1 *= kScale; }
          v0 = tf32_rna(v0);   // consumed by tensor-core attention
          v1 = tf32_rna(v1);
        } else {
          v0 += b0[n];
          v1 += b0[n + 1];
        }
        *(float2*)(C + (size_t)m * N + n) = make_float2(v0, v1);
      }
    }
  }
}

// ---------------------------------------------------------------------------
// Tensor-core attention (as R4) + __launch_bounds__(256, 2) for 2 CTAs/SM
// (smem 76.8KB x 2 = 153.6KB fits).
// ---------------------------------------------------------------------------
namespace {
constexpr int TQ   = 32;
constexpr int KC   = 128;
constexpr int SSTR = 260;   // S row stride
constexpr int QSTR = 68;    // Qs row stride (row-major 32x64)
constexpr int KSTR = 68;    // Ks row stride (row-major 128x64)
constexpr int VSTR = 132;   // Vs row stride (transposed 64x128)
constexpr int kKVFloats = (128 * KSTR > 64 * VSTR) ? 128 * KSTR : 64 * VSTR;  // 8704
constexpr int kAttnSmemFloats = TQ * SSTR + TQ * QSTR + kKVFloats;
constexpr int kAttnSmemBytes  = kAttnSmemFloats * 4;                // 76800
}  // namespace

__global__ __launch_bounds__(256, 2)
void attn_kernel() {
  extern __shared__ float smA[];
  float* S  = smA;                 // [32][SSTR]
  float* Qs = smA + TQ * SSTR;     // [32][QSTR]
  float* KV = Qs + TQ * QSTR;      // Ks [128][KSTR]  /  Vs [64][VSTR]

  const int t    = threadIdx.x;
  const int lane = t & 31;
  const int w    = t >> 5;
  const int tile = blockIdx.x;
  const int bh   = blockIdx.y;
  const int b    = bh / kHeads;
  const int h    = bh - b * kHeads;
  const int i0g  = tile * TQ;

  const float* Qb = g_qkv + (size_t)b * kTok * kQkvN + h * 64;
  const float* Kb = Qb + kDim;
  const float* Vb = Qb + 2 * kDim;

  const int lm = lane >> 2;   // 0..7
  const int lk = lane & 3;    // 0..3
  const int mrow = (w & 1) * 16;       // warp m offset within 32 rows

  // ---- load Q tile row-major: Qs[i][d] ----
  {
    int i  = t >> 3;
    int d0 = (t & 7) * 8;
    int qi = i0g + i;
    float4 v0 = {0.f, 0.f, 0.f, 0.f}, v1 = {0.f, 0.f, 0.f, 0.f};
    if (qi < kTok) {
      const float* p = Qb + (size_t)qi * kQkvN + d0;
      v0 = *(const float4*)p;
      v1 = *(const float4*)(p + 4);
    }
    *(float4*)&Qs[i * QSTR + d0]     = v0;
    *(float4*)&Qs[i * QSTR + d0 + 4] = v1;
  }
  __syncthreads();

  // ---- hoist Q fragments ----
  float aq[8][4];
#pragma unroll
  for (int ks = 0; ks < 8; ks++) {
    int r = mrow + lm;
    int c = ks * 8 + lk;
    aq[ks][0] = Qs[r * QSTR + c];
    aq[ks][1] = Qs[(r + 8) * QSTR + c];
    aq[ks][2] = Qs[r * QSTR + c + 4];
    aq[ks][3] = Qs[(r + 8) * QSTR + c + 4];
  }

  // ---- Phase A: S = Q @ K^T ----
  for (int c0 = 0; c0 < 2; c0++) {
    const int j0 = c0 * KC;
    {  // load K chunk row-major: Ks[j][d], zero-fill past kTok
      int j  = t >> 1;
      int d0 = (t & 1) * 32;
      int kj = j0 + j;
      const float* p = Kb + (size_t)kj * kQkvN + d0;
#pragma unroll
      for (int q = 0; q < 8; q++) {
        float4 v = {0.f, 0.f, 0.f, 0.f};
        if (kj < kTok) v = *(const float4*)(p + q * 4);
        *(float4*)&KV[j * KSTR + d0 + q * 4] = v;
      }
    }
    __syncthreads();

    float acc[4][4] = {};
#pragma unroll
    for (int ks = 0; ks < 8; ks++) {
#pragma unroll
      for (int nt = 0; nt < 4; nt++) {
        int n = ((w >> 1) * 4 + nt) * 8 + lm;   // key index within chunk
        int c = ks * 8 + lk;
        float bf[2] = {KV[n * KSTR + c], KV[n * KSTR + c + 4]};
        mma_tf32(acc[nt], aq[ks], bf);
      }
    }
#pragma unroll
    for (int nt = 0; nt < 4; nt++) {
      int col = j0 + ((w >> 1) * 4 + nt) * 8 + lk * 2;
      int r   = mrow + lm;
      *(float2*)&S[r * SSTR + col]       = make_float2(acc[nt][0], acc[nt][1]);
      *(float2*)&S[(r + 8) * SSTR + col] = make_float2(acc[nt][2], acc[nt][3]);
    }
    __syncthreads();
  }

  // ---- Phase B: softmax(S + rpb); write probs tf32-rounded ----
  {
#pragma unroll
    for (int r = 0; r < 4; r++) {
      int i  = w * 4 + r;
      int qi = min(i0g + i, kTok - 1);
      const float* rp = g_rpb + ((size_t)h * kTok + qi) * kTok;
      float vals[7];
      float mx = -1e30f;
#pragma unroll
      for (int k = 0; k < 7; k++) {
        int j = lane + k * 32;
        float v = -1e30f;
        if (j < kTok) v = S[i * SSTR + j] + rp[j];
        vals[k] = v;
        mx = fmaxf(mx, v);
      }
#pragma unroll
      for (int o = 16; o; o >>= 1) mx = fmaxf(mx, __shfl_xor_sync(0xffffffffu, mx, o));
      float sum = 0.f;
#pragma unroll
      for (int k = 0; k < 7; k++) {
        int j = lane + k * 32;
        float e = (j < kTok) ? __expf(vals[k] - mx) : 0.f;
        vals[k] = e;
        sum += e;
      }
#pragma unroll
      for (int o = 16; o; o >>= 1) sum += __shfl_xor_sync(0xffffffffu, sum, o);
      float inv = 1.f / sum;
#pragma unroll
      for (int k = 0; k < 7; k++) {
        int j = lane + k * 32;
        S[i * SSTR + j] = (j < kTok) ? tf32_rna(vals[k] * inv) : 0.f;
      }
      S[i * SSTR + 224 + lane] = 0.f;   // zero pad cols 224..255
    }
  }
  __syncthreads();

  // ---- Phase C: O = P @ V ----
  float accO[2][4] = {};
  for (int c0 = 0; c0 < 2; c0++) {
    const int j0 = c0 * KC;
    {  // load V chunk transposed: Vs[d][j], zero-fill past kTok
      int j  = t >> 1;
      int d0 = (t & 1) * 32;
      int vj = j0 + j;
      const float* p = Vb + (size_t)vj * kQkvN + d0;
#pragma unroll
      for (int q = 0; q < 8; q++) {
        float4 v = {0.f, 0.f, 0.f, 0.f};
        if (vj < kTok) v = *(const float4*)(p + q * 4);
        int d = d0 + q * 4;
        KV[(d + 0) * VSTR + j] = v.x;
        KV[(d + 1) * VSTR + j] = v.y;
        KV[(d + 2) * VSTR + j] = v.z;
        KV[(d + 3) * VSTR + j] = v.w;
      }
    }
    __syncthreads();

#pragma unroll
    for (int ks = 0; ks < 16; ks++) {
      int r = mrow + lm;
      int c = j0 + ks * 8 + lk;
      float ap[4];
      ap[0] = S[r * SSTR + c];
      ap[1] = S[(r + 8) * SSTR + c];
      ap[2] = S[r * SSTR + c + 4];
      ap[3] = S[(r + 8) * SSTR + c + 4];
#pragma unroll
      for (int nt = 0; nt < 2; nt++) {
        int n = ((w >> 1) * 2 + nt) * 8 + lm;   // d index 0..63
        int k = ks * 8 + lk;                    // j within chunk
        float bf[2] = {KV[n * VSTR + k], KV[n * VSTR + k + 4]};
        mma_tf32(accO[nt], ap, bf);
      }
    }
    __syncthreads();
  }

  // ---- epilogue: write g_attn (tf32-rounded for proj GEMM) ----
#pragma unroll
  for (int nt = 0; nt < 2; nt++) {
    int dcol = ((w >> 1) * 2 + nt) * 8 + lk * 2;
#pragma unroll
    for (int half = 0; half < 2; half++) {
      int i = i0g + mrow + lm + half * 8;
      if (i < kTok) {
        float v0 = tf32_rna(accO[nt][half * 2 + 0]);
        float v1 = tf32_rna(accO[nt][half * 2 + 1]);
        *(float2*)(g_attn + ((size_t)b * kTok + i) * kDim + h * 64 + dcol) =
            make_float2(v0, v1);
      }
    }
  }
}

// ---------------------------------------------------------------------------
// Launch
// ---------------------------------------------------------------------------
extern "C" void kernel_launch(void* const* d_in, const int* in_sizes, int n_in,
                              void* d_out, int out_size) {
  const float* x         = (const float*)d_in[0];
  const float* qkv_w     = (const float*)d_in[1];
  const float* q_bias    = (const float*)d_in[2];
  const float* v_bias    = (const float*)d_in[3];
  const float* rpb_table = (const float*)d_in[4];
  const float* proj_w    = (const float*)d_in[5];
  const float* proj_b    = (const float*)d_in[6];
  const int*   rel_idx   = (const int*)d_in[7];
  float* out = (float*)d_out;

  float *qkv_ptr, *attn_ptr, *x_ptr, *wqkv_ptr, *wproj_ptr;
  cudaGetSymbolAddress((void**)&qkv_ptr, g_qkv);
  cudaGetSymbolAddress((void**)&attn_ptr, g_attn);
  cudaGetSymbolAddress((void**)&x_ptr, g_x);
  cudaGetSymbolAddress((void**)&wqkv_ptr, g_wqkv);
  cudaGetSymbolAddress((void**)&wproj_ptr, g_wproj);

  // (0) tf32-round GEMM inputs
  {
    int n4 = kM * kDim / 4;
    tf32_round_kernel<<<(n4 + 255) / 256, 256>>>(x, x_ptr, n4);
    n4 = kQkvN * kDim / 4;
    tf32_round_kernel<<<(n4 + 255) / 256, 256>>>(qkv_w, wqkv_ptr, n4);
    n4 = kDim * kDim / 4;
    tf32_round_kernel<<<(n4 + 255) / 256, 256>>>(proj_w, wproj_ptr, n4);
  }

  // (1) relative position bias expansion
  rpb_expand<<<(kTok * kTok + 255) / 256, 256>>>(rel_idx, rpb_table);

  // (2) QKV projection (epilogue rounds to tf32)
  cudaFuncSetAttribute(gemm_tf32_pipe<0>, cudaFuncAttributeMaxDynamicSharedMemorySize,
                       kGemmSmemBytes);
  {
    dim3 grid(kQkvN / 128, (kM + 127) / 128);
    gemm_tf32_pipe<0><<<grid, 256, kGemmSmemBytes>>>(x_ptr, wqkv_ptr, qkv_ptr,
                                                     kM, kDim, kQkvN, q_bias, v_bias);
  }

  // (3) tensor-core attention
  cudaFuncSetAttribute(attn_kernel, cudaFuncAttributeMaxDynamicSharedMemorySize,
                       kAttnSmemBytes);
  attn_kernel<<<dim3(7, kBatch * kHeads), 256, kAttnSmemBytes>>>();

  // (4) output projection
  cudaFuncSetAttribute(gemm_tf32_pipe<1>, cudaFuncAttributeMaxDynamicSharedMemorySize,
                       kGemmSmemBytes);
  {
    dim3 grid(kDim / 128, (kM + 127) / 128);
    gemm_tf32_pipe<1><<<grid, 256, kGemmSmemBytes>>>(attn_ptr, wproj_ptr, out,
                                                     kM, kDim, kDim, proj_b, nullptr);
  }
}

// round 10
// speedup vs baseline: 2.1479x; 2.1479x over previous
#include <cuda_runtime.h>
#include <cuda_fp16.h>
#include <cstdint>

// ---------------------------------------------------------------------------
// Problem constants
// ---------------------------------------------------------------------------
namespace {
constexpr int kHeads = 12;
constexpr int kTok   = 197;               // N_PATCH + 1
constexpr int kDim   = 768;
constexpr int kBatch = 64;
constexpr int kM     = kBatch * kTok;     // 12608
constexpr int kQkvN  = 3 * kDim;          // 2304
constexpr float kScale = 0.125f;          // hd^-0.5
}  // namespace

// Scratch (static device globals; no runtime allocation allowed)
__device__ __half g_qkv[(size_t)kM * kQkvN];            // (B, N, 3C) fp16
__device__ __half g_attn[(size_t)kM * kDim];            // (B, N, C) fp16
__device__ float  g_rpb[(size_t)kHeads * kTok * kTok];  // (H, N, N) fp32
__device__ __half g_x[(size_t)kM * kDim];               // fp16 x
__device__ __half g_wqkv[(size_t)kQkvN * kDim];         // fp16 qkv_w
__device__ __half g_wproj[(size_t)kDim * kDim];         // fp16 proj_w

// ---------------------------------------------------------------------------
// Elementwise fp32 -> fp16 conversion (n divisible by 4)
// ---------------------------------------------------------------------------
__global__ void f2h_kernel(const float* __restrict__ in, __half* __restrict__ out,
                           int n4) {
  int i = blockIdx.x * blockDim.x + threadIdx.x;
  if (i >= n4) return;
  float4 v = ((const float4*)in)[i];
  __half2 h0 = __floats2half2_rn(v.x, v.y);
  __half2 h1 = __floats2half2_rn(v.z, v.w);
  ((__half2*)out)[i * 2 + 0] = h0;
  ((__half2*)out)[i * 2 + 1] = h1;
}

// ---------------------------------------------------------------------------
// Relative position bias expansion: g_rpb[h][i][j] = table[idx[i][j]][h]
// ---------------------------------------------------------------------------
__global__ void rpb_expand(const int* __restrict__ idx, const float* __restrict__ tbl) {
  int t = blockIdx.x * blockDim.x + threadIdx.x;
  if (t >= kTok * kTok) return;
  int id = idx[t];
#pragma unroll
  for (int h = 0; h < kHeads; h++)
    g_rpb[(size_t)h * kTok * kTok + t] = tbl[id * kHeads + h];
}

// ---------------------------------------------------------------------------
// mma / ldmatrix helpers
// ---------------------------------------------------------------------------
__device__ __forceinline__ void mma_f16(float (&d)[4], const uint32_t* a,
                                        const uint32_t* b) {
  asm volatile(
      "mma.sync.aligned.m16n8k16.row.col.f32.f16.f16.f32 "
      "{%0,%1,%2,%3}, {%4,%5,%6,%7}, {%8,%9}, {%0,%1,%2,%3};"
      : "+f"(d[0]), "+f"(d[1]), "+f"(d[2]), "+f"(d[3])
      : "r"(a[0]), "r"(a[1]), "r"(a[2]), "r"(a[3]), "r"(b[0]), "r"(b[1]));
}

__device__ __forceinline__ void ldm_x4(uint32_t (&r)[4], uint32_t addr) {
  asm volatile("ldmatrix.sync.aligned.m8n8.x4.shared.b16 {%0,%1,%2,%3}, [%4];"
               : "=r"(r[0]), "=r"(r[1]), "=r"(r[2]), "=r"(r[3]) : "r"(addr));
}

__device__ __forceinline__ void cp_async16(uint32_t dst, const void* src, bool pred) {
  int sz = pred ? 16 : 0;
  asm volatile("cp.async.ca.shared.global [%0], [%1], 16, %2;"
               :: "r"(dst), "l"(src), "r"(sz));
}
__device__ __forceinline__ void cp_commit() { asm volatile("cp.async.commit_group;"); }
__device__ __forceinline__ void cp_wait2()  { asm volatile("cp.async.wait_group 2;"); }

// ---------------------------------------------------------------------------
// FP16 tensor-core GEMM, cp.async 4-stage pipeline, m16n8k16 + ldmatrix.
//   C[m][n] = sum_k A[m][k] * W[n][k]  (+bias epilogue)
// Block tile 128x128x32(half), 256 threads = 8 warps (2x4), warp tile 64x32.
// SMEM rows: 32 halfs data, stride 40 halfs (80B = 5x16B -> ldmatrix phases
// hit 8 distinct 16B banks; conflict-free).
// MODE 0: qkv epilogue (bias [q_bias,0,v_bias], q scaled), half output
// MODE 1: proj epilogue (bias b0), float output
// ---------------------------------------------------------------------------
namespace {
constexpr int kStages       = 4;
constexpr int kSmStrideH    = 40;                       // halfs per row
constexpr int kStageBytes   = 2 * 128 * kSmStrideH * 2; // A + B = 20480
constexpr int kGemmSmemBytes = kStages * kStageBytes;   // 81920
}  // namespace

template <int MODE>
__global__ __launch_bounds__(256, 2)
void gemm_f16(const __half* __restrict__ A, const __half* __restrict__ W,
              void* __restrict__ Cv, int M, int K, int N,
              const float* __restrict__ b0, const float* __restrict__ b1) {
  extern __shared__ __align__(16) unsigned char smraw[];

  const int t    = threadIdx.x;
  const int lane = t & 31;
  const int wid  = t >> 5;
  const int wm   = (wid >> 2) * 64;
  const int wn   = (wid & 3) * 32;
  const int m0   = blockIdx.y * 128;
  const int n0   = blockIdx.x * 128;

  const uint32_t sb = (uint32_t)__cvta_generic_to_shared(smraw);

  auto issue_stage = [&](int c) {
    uint32_t base = sb + (uint32_t)(c & 3) * kStageBytes;
    int k0 = c * 32;
#pragma unroll
    for (int i = 0; i < 2; i++) {
      int idx = t + i * 256;
      int row = idx >> 2;          // 0..127
      int j   = idx & 3;           // 16B chunk (8 halfs)
      uint32_t off = (uint32_t)(row * kSmStrideH * 2 + j * 16);
      int mg = m0 + row;
      cp_async16(base + off, A + (size_t)mg * K + k0 + j * 8, mg < M);
      cp_async16(base + 128 * kSmStrideH * 2 + off,
                 W + (size_t)(n0 + row) * K + k0 + j * 8, true);
    }
  };

  const int nkb = K / 32;   // 24
#pragma unroll
  for (int s = 0; s < kStages - 1; s++) { issue_stage(s); cp_commit(); }

  float acc[4][4][4] = {};

  // per-thread ldmatrix address components (tile tau = lane>>3)
  const int l7  = lane & 7;
  const int a_row = wm + l7 + ((lane >> 3) & 1) * 8;   // + mt*16
  const int a_col = ((lane >> 4) & 1) * 8;             // + ks*16
  const int b_row = wn + ((lane >> 4) & 1) * 8 + l7;   // + pair*16
  const int b_col = ((lane >> 3) & 1) * 8;             // + ks*16

  for (int kb = 0; kb < nkb; kb++) {
    cp_wait2();
    __syncthreads();
    if (kb + kStages - 1 < nkb) issue_stage(kb + kStages - 1);
    cp_commit();

    const uint32_t Ab = sb + (uint32_t)(kb & 3) * kStageBytes;
    const uint32_t Bb = Ab + 128 * kSmStrideH * 2;

#pragma unroll
    for (int ks = 0; ks < 2; ks++) {
      uint32_t af[4][4], bf[2][4];
#pragma unroll
      for (int mt = 0; mt < 4; mt++)
        ldm_x4(af[mt], Ab + (uint32_t)(((a_row + mt * 16) * kSmStrideH +
                                        ks * 16 + a_col) * 2));
#pragma unroll
      for (int p = 0; p < 2; p++)
        ldm_x4(bf[p], Bb + (uint32_t)(((b_row + p * 16) * kSmStrideH +
                                       ks * 16 + b_col) * 2));
#pragma unroll
      for (int mt = 0; mt < 4; mt++)
#pragma unroll
        for (int nt = 0; nt < 4; nt++)
          mma_f16(acc[mt][nt], af[mt], &bf[nt >> 1][(nt & 1) * 2]);
    }
  }

  // ---- epilogue ----
  const int mrow = lane >> 2;
  const int ncol = (lane & 3) * 2;
#pragma unroll
  for (int mt = 0; mt < 4; mt++) {
#pragma unroll
    for (int half_ = 0; half_ < 2; half_++) {
      int m = m0 + wm + mt * 16 + mrow + half_ * 8;
      if (m >= M) continue;
#pragma unroll
      for (int nt = 0; nt < 4; nt++) {
        int n = n0 + wn + nt * 8 + ncol;
        float v0 = acc[mt][nt][half_ * 2 + 0];
        float v1 = acc[mt][nt][half_ * 2 + 1];
        if (MODE == 0) {
          float bias0 = (n < kDim) ? b0[n] : ((n < 2 * kDim) ? 0.f : b1[n - 2 * kDim]);
          float bias1 = (n + 1 < kDim) ? b0[n + 1]
                        : ((n + 1 < 2 * kDim) ? 0.f : b1[n + 1 - 2 * kDim]);
          v0 += bias0; v1 += bias1;
          if (n < kDim) { v0 *= kScale; v1 *= kScale; }
          __half* C = (__half*)Cv;
          *(__half2*)(C + (size_t)m * N + n) = __floats2half2_rn(v0, v1);
        } else {
          float* C = (float*)Cv;
          v0 += b0[n]; v1 += b0[n + 1];
          *(float2*)(C + (size_t)m * N + n) = make_float2(v0, v1);
        }
      }
    }
  }
}

// ---------------------------------------------------------------------------
// FP16 tensor-core attention. One block = (b,h) x 32 query rows, 8 warps.
// Phase A: S[32x256] = Q @ K^T (m16n8k16, ldmatrix; warp tile 16x32)
// Phase B: fp32 softmax(S + rpb) -> probs stored fp16 in Ph
// Phase C: O[32x64] = P @ V (warp tile 16x16, V staged transposed)
// Strides (halfs): Qs 72 (144B), Ks 72, Ph 264 (528B), Vt 136 (272B) — all
// odd multiples of 16B -> ldmatrix conflict-free.
// ---------------------------------------------------------------------------
namespace {
constexpr int TQ    = 32;
constexpr int KC    = 128;
constexpr int SSTR  = 260;   // S (float) row stride
constexpr int QSTRH = 72;
constexpr int KSTRH = 72;
constexpr int PSTRH = 264;
constexpr int VSTRH = 136;
constexpr int kOffQs = TQ * SSTR * 4;                 // 33280
constexpr int kOffPh = kOffQs + TQ * QSTRH * 2;       // +4608 = 37888
constexpr int kOffKV = kOffPh + TQ * PSTRH * 2;       // +16896 = 54784
constexpr int kKVBytes = 128 * KSTRH * 2;             // 18432 (>= Vt 17408)
constexpr int kAttnSmemBytes = kOffKV + kKVBytes;     // 73216
}  // namespace

__global__ __launch_bounds__(256, 2)
void attn_kernel() {
  extern __shared__ __align__(16) unsigned char smraw[];
  float*  S  = (float*)smraw;
  __half* Qs = (__half*)(smraw + kOffQs);
  __half* Ph = (__half*)(smraw + kOffPh);
  __half* KV = (__half*)(smraw + kOffKV);

  const int t    = threadIdx.x;
  const int lane = t & 31;
  const int w    = t >> 5;
  const int tile = blockIdx.x;
  const int bh   = blockIdx.y;
  const int b    = bh / kHeads;
  const int h    = bh - b * kHeads;
  const int i0g  = tile * TQ;

  const __half* Qb = g_qkv + (size_t)b * kTok * kQkvN + h * 64;
  const __half* Kb = Qb + kDim;
  const __half* Vb = Qb + 2 * kDim;

  const uint32_t uQs = (uint32_t)__cvta_generic_to_shared(Qs);
  const uint32_t uPh = (uint32_t)__cvta_generic_to_shared(Ph);
  const uint32_t uKV = (uint32_t)__cvta_generic_to_shared(KV);

  const int l7   = lane & 7;
  const int mrow = (w & 1) * 16;
  const int a_row = mrow + l7 + ((lane >> 3) & 1) * 8;
  const int a_col = ((lane >> 4) & 1) * 8;
  const int b_rowoff = ((lane >> 4) & 1) * 8 + l7;   // + ntile-pair base
  const int b_col    = ((lane >> 3) & 1) * 8;
  const int lm = lane >> 2;
  const int lk = lane & 3;

  // ---- load Q tile: Qs[i][d] (32x64 halfs) ----
  {
    int i  = t >> 3;
    int d0 = (t & 7) * 8;
    int qi = i0g + i;
    uint4 v = {0u, 0u, 0u, 0u};
    if (qi < kTok) v = *(const uint4*)(Qb + (size_t)qi * kQkvN + d0);
    *(uint4*)&Qs[i * QSTRH + d0] = v;
  }
  __syncthreads();

  // ---- hoist Q fragments: 4 ksteps of k16 over d=64 ----
  uint32_t aq[4][4];
#pragma unroll
  for (int ks = 0; ks < 4; ks++)
    ldm_x4(aq[ks], uQs + (uint32_t)((a_row * QSTRH + ks * 16 + a_col) * 2));

  // ---- Phase A: S = Q @ K^T ----
  for (int c0 = 0; c0 < 2; c0++) {
    const int j0 = c0 * KC;
    {  // load K chunk: Ks[j][d] (128x64 halfs), zero-fill past kTok
      int j  = t >> 1;
      int d0 = (t & 1) * 32;
      int kj = j0 + j;
      const __half* p = Kb + (size_t)kj * kQkvN + d0;
#pragma unroll
      for (int q = 0; q < 4; q++) {
        uint4 v = {0u, 0u, 0u, 0u};
        if (kj < kTok) v = *(const uint4*)(p + q * 8);
        *(uint4*)&KV[j * KSTRH + d0 + q * 8] = v;
      }
    }
    __syncthreads();

    float acc[4][4] = {};
#pragma unroll
    for (int ks = 0; ks < 4; ks++) {
      uint32_t bf[2][4];
#pragma unroll
      for (int p = 0; p < 2; p++) {
        int nb = (w >> 1) * 32 + p * 16;   // key-row base for this ldmatrix pair
        ldm_x4(bf[p], uKV + (uint32_t)(((nb + b_rowoff) * KSTRH +
                                        ks * 16 + b_col) * 2));
      }
#pragma unroll
      for (int nt = 0; nt < 4; nt++)
        mma_f16(acc[nt], aq[ks], &bf[nt >> 1][(nt & 1) * 2]);
    }
#pragma unroll
    for (int nt = 0; nt < 4; nt++) {
      int col = j0 + ((w >> 1) * 4 + nt) * 8 + lk * 2;
      int r   = mrow + lm;
      *(float2*)&S[r * SSTR + col]       = make_float2(acc[nt][0], acc[nt][1]);
      *(float2*)&S[(r + 8) * SSTR + col] = make_float2(acc[nt][2], acc[nt][3]);
    }
    __syncthreads();
  }

  // ---- Phase B: softmax(S + rpb) in fp32, write probs fp16 to Ph ----
  {
#pragma unroll
    for (int r = 0; r < 4; r++) {
      int i  = w * 4 + r;
      int qi = min(i0g + i, kTok - 1);
      const float* rp = g_rpb + ((size_t)h * kTok + qi) * kTok;
      float vals[7];
      float mx = -1e30f;
#pragma unroll
      for (int k = 0; k < 7; k++) {
        int j = lane + k * 32;
        float v = -1e30f;
        if (j < kTok) v = S[i * SSTR + j] + rp[j];
        vals[k] = v;
        mx = fmaxf(mx, v);
      }
#pragma unroll
      for (int o = 16; o; o >>= 1) mx = fmaxf(mx, __shfl_xor_sync(0xffffffffu, mx, o));
      float sum = 0.f;
#pragma unroll
      for (int k = 0; k < 7; k++) {
        int j = lane + k * 32;
        float e = (j < kTok) ? __expf(vals[k] - mx) : 0.f;
        vals[k] = e;
        sum += e;
      }
#pragma unroll
      for (int o = 16; o; o >>= 1) sum += __shfl_xor_sync(0xffffffffu, sum, o);
      float inv = 1.f / sum;
#pragma unroll
      for (int k = 0; k < 7; k++) {
        int j = lane + k * 32;
        Ph[i * PSTRH + j] = __float2half_rn((j < kTok) ? vals[k] * inv : 0.f);
      }
      Ph[i * PSTRH + 224 + lane] = __float2half_rn(0.f);
    }
  }
  __syncthreads();

  // ---- Phase C: O = P @ V ----
  float accO[2][4] = {};
  for (int c0 = 0; c0 < 2; c0++) {
    const int j0 = c0 * KC;
    {  // load V chunk transposed: Vt[d][j] (64x128 halfs), zero past kTok
      int j  = t >> 1;
      int d0 = (t & 1) * 32;
      int vj = j0 + j;
      const __half* p = Vb + (size_t)vj * kQkvN + d0;
#pragma unroll
      for (int q = 0; q < 4; q++) {
        uint4 raw = {0u, 0u, 0u, 0u};
        if (vj < kTok) raw = *(const uint4*)(p + q * 8);
        const __half* hp = (const __half*)&raw;
#pragma unroll
        for (int e = 0; e < 8; e++)
          KV[(d0 + q * 8 + e) * VSTRH + j] = hp[e];
      }
    }
    __syncthreads();

#pragma unroll
    for (int ks = 0; ks < 8; ks++) {
      uint32_t ap[4], bv[4];
      ldm_x4(ap, uPh + (uint32_t)((a_row * PSTRH + j0 + ks * 16 + a_col) * 2));
      {
        int nb = (w >> 1) * 16;   // d-row base (two 8-wide ntiles)
        ldm_x4(bv, uKV + (uint32_t)(((nb + b_rowoff) * VSTRH +
                                     ks * 16 + b_col) * 2));
      }
#pragma unroll
      for (int nt = 0; nt < 2; nt++)
        mma_f16(accO[nt], ap, &bv[nt * 2]);
    }
    __syncthreads();
  }

  // ---- epilogue: write g_attn (fp16) ----
#pragma unroll
  for (int nt = 0; nt < 2; nt++) {
    int dcol = ((w >> 1) * 2 + nt) * 8 + lk * 2;
#pragma unroll
    for (int half_ = 0; half_ < 2; half_++) {
      int i = i0g + mrow + lm + half_ * 8;
      if (i < kTok) {
        __half2 hv = __floats2half2_rn(accO[nt][half_ * 2 + 0],
                                       accO[nt][half_ * 2 + 1]);
        *(__half2*)(g_attn + ((size_t)b * kTok + i) * kDim + h * 64 + dcol) = hv;
      }
    }
  }
}

// ---------------------------------------------------------------------------
// Launch
// ---------------------------------------------------------------------------
extern "C" void kernel_launch(void* const* d_in, const int* in_sizes, int n_in,
                              void* d_out, int out_size) {
  const float* x         = (const float*)d_in[0];
  const float* qkv_w     = (const float*)d_in[1];
  const float* q_bias    = (const float*)d_in[2];
  const float* v_bias    = (const float*)d_in[3];
  const float* rpb_table = (const float*)d_in[4];
  const float* proj_w    = (const float*)d_in[5];
  const float* proj_b    = (const float*)d_in[6];
  const int*   rel_idx   = (const int*)d_in[7];
  float* out = (float*)d_out;

  __half *qkv_ptr, *attn_ptr, *x_ptr, *wqkv_ptr, *wproj_ptr;
  cudaGetSymbolAddress((void**)&qkv_ptr, g_qkv);
  cudaGetSymbolAddress((void**)&attn_ptr, g_attn);
  cudaGetSymbolAddress((void**)&x_ptr, g_x);
  cudaGetSymbolAddress((void**)&wqkv_ptr, g_wqkv);
  cudaGetSymbolAddress((void**)&wproj_ptr, g_wproj);

  // (0) fp32 -> fp16 conversion of GEMM inputs
  {
    int n4 = kM * kDim / 4;
    f2h_kernel<<<(n4 + 255) / 256, 256>>>(x, x_ptr, n4);
    n4 = kQkvN * kDim / 4;
    f2h_kernel<<<(n4 + 255) / 256, 256>>>(qkv_w, wqkv_ptr, n4);
    n4 = kDim * kDim / 4;
    f2h_kernel<<<(n4 + 255) / 256, 256>>>(proj_w, wproj_ptr, n4);
  }

  // (1) relative position bias expansion
  rpb_expand<<<(kTok * kTok + 255) / 256, 256>>>(rel_idx, rpb_table);

  // (2) QKV projection (fp16 in, fp16 out with bias + q-scale)
  cudaFuncSetAttribute(gemm_f16<0>, cudaFuncAttributeMaxDynamicSharedMemorySize,
                       kGemmSmemBytes);
  {
    dim3 grid(kQkvN / 128, (kM + 127) / 128);
    gemm_f16<0><<<grid, 256, kGemmSmemBytes>>>(x_ptr, wqkv_ptr, qkv_ptr,
                                               kM, kDim, kQkvN, q_bias, v_bias);
  }

  // (3) fp16 tensor-core attention
  cudaFuncSetAttribute(attn_kernel, cudaFuncAttributeMaxDynamicSharedMemorySize,
                       kAttnSmemBytes);
  attn_kernel<<<dim3(7, kBatch * kHeads), 256, kAttnSmemBytes>>>();

  // (4) output projection (fp16 in, fp32 out with bias)
  cudaFuncSetAttribute(gemm_f16<1>, cudaFuncAttributeMaxDynamicSharedMemorySize,
                       kGemmSmemBytes);
  {
    dim3 grid(kDim / 128, (kM + 127) / 128);
    gemm_f16<1><<<grid, 256, kGemmSmemBytes>>>(attn_ptr, wproj_ptr, out,
                                               kM, kDim, kDim, proj_b, nullptr);
  }
}